// round 11
// baseline (speedup 1.0000x reference)
#include <cuda_runtime.h>
#include <math.h>

// ---------------- problem constants ----------------
#define Bn    2
#define Cin   32
#define Cout  64
#define Dd    48
#define Hh    48
#define Ww    48
#define HWc   (Hh*Ww)          // 2304
#define Ss    (Dd*Hh*Ww)       // 110592
#define NPTS  (Bn*Ss)          // 221184
#define NBLK  (NPTS/128)       // 1728 point-kernel blocks
#define BPB   (Ss/128)         // 864 blocks per batch
#define EPSf  1e-5f

// ---------------- scratch (no runtime allocation) ----------------
__device__ float g_xT[Bn*Ss*Cin];          // x transposed to (b,d,h,w,c)  ~28MB
__device__ float g_off_raw[Bn*6*Ss];       // raw offset-conv, channels 3..8 ~5.3MB
__device__ float g_conv_out[Bn*Cout*Ss];   // pre-GN conv output ~56.6MB
__device__ float g_bn_part[12*NBLK];
__device__ float g_bn_red[12];
__device__ float g_bn_scale[6];
__device__ float g_bn_shift[6];
__device__ float g_gn_part[64*BPB];        // (b*32 + slot)*BPB + blk
__device__ float g_gn_red[64];
__device__ float g_gn_a[Bn*Cout];
__device__ float g_gn_b[Bn*Cout];

// ---------------- packed f32x2 helpers ----------------
__device__ __forceinline__ unsigned long long pack2(float x, float y) {
    unsigned long long r;
    asm("mov.b64 %0, {%1, %2};" : "=l"(r) : "f"(x), "f"(y));
    return r;
}
__device__ __forceinline__ float2 unpack2(unsigned long long v) {
    float2 r;
    asm("mov.b64 {%0, %1}, %2;" : "=f"(r.x), "=f"(r.y) : "l"(v));
    return r;
}
__device__ __forceinline__ void ffma2u(unsigned long long& d,
                                       unsigned long long a,
                                       unsigned long long b) {
    asm("fma.rn.f32x2 %0, %1, %2, %0;" : "+l"(d) : "l"(a), "l"(b));
}

// ---------------- kernel 1: NCDHW -> NDHWC transpose ----------------
__global__ void k_transpose(const float* __restrict__ x) {
    __shared__ float s[32][33];
    int tile = blockIdx.x;
    int wt   = tile & 1;
    int bh   = tile >> 1;                 // b*Dd*Hh + d*Hh + h
    int b    = bh / (Dd*Hh);
    int dhh  = bh - b*(Dd*Hh);
    int w0   = wt * 32;
    int tx = threadIdx.x, ty = threadIdx.y;

    int w = w0 + tx;
    if (w < Ww)
        s[ty][tx] = x[((size_t)(b*Cin + ty))*Ss + dhh*Ww + w];
    __syncthreads();
    int w2 = w0 + ty;
    if (w2 < Ww)
        g_xT[((size_t)(b*Ss) + dhh*Ww + w2)*Cin + tx] = s[tx][ty];
}

// ---------------- kernel 2: offset conv (3x3x3, SAME), 6 live channels ----------------
// Writes raw conv output + deterministic per-block BN partial sums.
__global__ void __launch_bounds__(128) k_offconv(const float* __restrict__ ow,
                                                 const float* __restrict__ ob) {
    __shared__ __align__(16) float2 s_w[27*16*6];  // [(tap*16+c2)*6 + j]
    __shared__ float s_bias[6];
    __shared__ float s_warp[4][12];

    int tid = threadIdx.x;
    for (int idx = tid; idx < 27*16*6; idx += 128) {
        int j   = idx % 6;
        int c2  = (idx / 6) % 16;
        int tap = idx / 96;
        float a = ow[(3+j)*(Cin*27) + (2*c2  )*27 + tap];
        float bb= ow[(3+j)*(Cin*27) + (2*c2+1)*27 + tap];
        s_w[idx] = make_float2(a, bb);
    }
    if (tid < 6) s_bias[tid] = ob[3+tid];
    __syncthreads();

    int p  = blockIdx.x * 128 + tid;
    int b  = p / Ss;
    int rr = p - b*Ss;
    int d  = rr / HWc;
    int hw = rr - d*HWc;
    int h  = hw / Ww;
    int w  = hw - h*Ww;

    unsigned long long acc[6];
#pragma unroll
    for (int j = 0; j < 6; j++) acc[j] = 0ULL;

    const float* xb = &g_xT[(size_t)b * Ss * Cin];
    for (int kd = 0; kd < 3; kd++) {
        int zz = d + kd - 1; if ((unsigned)zz >= Dd) continue;
        for (int kh = 0; kh < 3; kh++) {
            int yy = h + kh - 1; if ((unsigned)yy >= Hh) continue;
            for (int kw = 0; kw < 3; kw++) {
                int xx = w + kw - 1; if ((unsigned)xx >= Ww) continue;
                int tap = kd*9 + kh*3 + kw;
                const float4* vp = (const float4*)&xb[(zz*HWc + yy*Ww + xx)*Cin];
                const ulonglong2* wp = (const ulonglong2*)&s_w[(tap*16)*6];
#pragma unroll
                for (int c4 = 0; c4 < 8; c4++) {
                    float4 v = vp[c4];
                    unsigned long long va = pack2(v.x, v.y);
                    unsigned long long vb = pack2(v.z, v.w);
                    const ulonglong2* wq = wp + (2*c4)*3;   // 6 float2 per c2
                    ulonglong2 a0 = wq[0], a1 = wq[1], a2 = wq[2];
                    ffma2u(acc[0], va, a0.x); ffma2u(acc[1], va, a0.y);
                    ffma2u(acc[2], va, a1.x); ffma2u(acc[3], va, a1.y);
                    ffma2u(acc[4], va, a2.x); ffma2u(acc[5], va, a2.y);
                    ulonglong2 b0 = wq[3], b1 = wq[4], b2 = wq[5];
                    ffma2u(acc[0], vb, b0.x); ffma2u(acc[1], vb, b0.y);
                    ffma2u(acc[2], vb, b1.x); ffma2u(acc[3], vb, b1.y);
                    ffma2u(acc[4], vb, b2.x); ffma2u(acc[5], vb, b2.y);
                }
            }
        }
    }

    float red[12];
#pragma unroll
    for (int j = 0; j < 6; j++) {
        float2 a = unpack2(acc[j]);
        float v = a.x + a.y + s_bias[j];
        g_off_raw[(size_t)(b*6 + j)*Ss + rr] = v;
        red[j]     = v;
        red[6 + j] = v * v;
    }

    int lane = tid & 31, wid = tid >> 5;
#pragma unroll
    for (int r = 0; r < 12; r++) {
        float t = red[r];
        t += __shfl_down_sync(0xffffffffu, t, 16);
        t += __shfl_down_sync(0xffffffffu, t, 8);
        t += __shfl_down_sync(0xffffffffu, t, 4);
        t += __shfl_down_sync(0xffffffffu, t, 2);
        t += __shfl_down_sync(0xffffffffu, t, 1);
        if (lane == 0) s_warp[wid][r] = t;
    }
    __syncthreads();
    if (tid < 12)
        g_bn_part[tid*NBLK + blockIdx.x] =
            s_warp[0][tid] + s_warp[1][tid] + s_warp[2][tid] + s_warp[3][tid];
}

// ---------------- kernel 3a: deterministic BN partial reduce ----------------
__global__ void k_bnred() {
    __shared__ float sh[256];
    int s = blockIdx.x;                   // 0..11
    float a = 0.f;
    for (int i = threadIdx.x; i < NBLK; i += 256)
        a += g_bn_part[s*NBLK + i];
    sh[threadIdx.x] = a;
    __syncthreads();
    for (int st = 128; st; st >>= 1) {
        if (threadIdx.x < st) sh[threadIdx.x] += sh[threadIdx.x + st];
        __syncthreads();
    }
    if (threadIdx.x == 0) g_bn_red[s] = sh[0];
}

// ---------------- kernel 3b: BN finalize ----------------
__global__ void k_bnfin(const float* __restrict__ bng, const float* __restrict__ bnb) {
    int j = threadIdx.x;
    if (j < 6) {
        float n    = (float)NPTS;
        float mean = g_bn_red[j] / n;
        float var  = g_bn_red[6 + j] / n - mean*mean;
        float sc   = bng[3 + j] * rsqrtf(fmaxf(var, 0.f) + EPSf);
        g_bn_scale[j] = sc;
        g_bn_shift[j] = bnb[3 + j] - mean * sc;
    }
}

// ---------------- kernel 4: fused BN+tanh+offsets+bilinear sample+1x1xK conv ----------------
__global__ void __launch_bounds__(128) k_sampconv(const float* __restrict__ cw,
                                                  const float* __restrict__ cb) {
    __shared__ __align__(16) float2 s_cw[3*32*32];  // [(k*32+c)*32 + o2]
    __shared__ float2 s_cb[32];
    __shared__ float  s_warp[4][32];

    int tid = threadIdx.x;
    for (int idx = tid; idx < 3072; idx += 128) {
        int o2 = idx & 31;
        int c  = (idx >> 5) & 31;
        int k  = idx >> 10;
        s_cw[idx] = make_float2(cw[(2*o2  )*96 + c*3 + k],
                                cw[(2*o2+1)*96 + c*3 + k]);
    }
    if (tid < 32) s_cb[tid] = make_float2(cb[2*tid], cb[2*tid+1]);
    __syncthreads();

    int p  = blockIdx.x * 128 + tid;
    int b  = p / Ss;
    int rr = p - b*Ss;
    int d  = rr / HWc;
    int hw = rr - d*HWc;
    int h  = hw / Ww;
    int w  = hw - h*Ww;

    // BN + tanh on the 6 live offset channels
    float off[6];
#pragma unroll
    for (int j = 0; j < 6; j++) {
        float raw = g_off_raw[(size_t)(b*6 + j)*Ss + rr];
        off[j] = tanhf(fmaf(raw, g_bn_scale[j], g_bn_shift[j]));
    }
    // K=3 cumulative offsets: center k=1 is zero, edges are single taps
    float cy[3] = { off[0], 0.f, off[2] };
    float cx[3] = { off[3], 0.f, off[5] };

    unsigned long long acc[32];
#pragma unroll
    for (int i = 0; i < 32; i++)
        acc[i] = pack2(s_cb[i].x, s_cb[i].y);

    const float* xb = &g_xT[(size_t)b * Ss * Cin];

    for (int k = 0; k < 3; k++) {
        int z = d + k - 1;
        z = max(0, min(z, Dd - 1));                         // integer z -> bilinear
        float yf = fminf(fmaxf((float)h + cy[k], 0.f), (float)(Hh - 1));
        float xf = fminf(fmaxf((float)w + cx[k], 0.f), (float)(Ww - 1));
        float y0f = floorf(yf), x0f = floorf(xf);
        float wy = yf - y0f, wx = xf - x0f;
        int y0 = (int)y0f, x0 = (int)x0f;
        int y1 = min(y0 + 1, Hh - 1), x1 = min(x0 + 1, Ww - 1);
        float w00 = (1.f - wy) * (1.f - wx);
        float w01 = (1.f - wy) * wx;
        float w10 = wy * (1.f - wx);
        float w11 = wy * wx;

        const float4* p00 = (const float4*)&xb[(z*HWc + y0*Ww + x0)*Cin];
        const float4* p01 = (const float4*)&xb[(z*HWc + y0*Ww + x1)*Cin];
        const float4* p10 = (const float4*)&xb[(z*HWc + y1*Ww + x0)*Cin];
        const float4* p11 = (const float4*)&xb[(z*HWc + y1*Ww + x1)*Cin];
        const ulonglong2* wk = (const ulonglong2*)&s_cw[k*1024];

        for (int c4 = 0; c4 < 8; c4++) {
            float4 a = p00[c4], bb = p01[c4], cc = p10[c4], dd = p11[c4];
            float s[4];
            s[0] = fmaf(w00, a.x, fmaf(w01, bb.x, fmaf(w10, cc.x, w11*dd.x)));
            s[1] = fmaf(w00, a.y, fmaf(w01, bb.y, fmaf(w10, cc.y, w11*dd.y)));
            s[2] = fmaf(w00, a.z, fmaf(w01, bb.z, fmaf(w10, cc.z, w11*dd.z)));
            s[3] = fmaf(w00, a.w, fmaf(w01, bb.w, fmaf(w10, cc.w, w11*dd.w)));
#pragma unroll
            for (int t = 0; t < 4; t++) {
                unsigned long long sv = pack2(s[t], s[t]);
                const ulonglong2* wr = wk + (c4*4 + t)*16;
#pragma unroll
                for (int i = 0; i < 16; i++) {
                    ulonglong2 ww = wr[i];
                    ffma2u(acc[2*i  ], sv, ww.x);
                    ffma2u(acc[2*i+1], sv, ww.y);
                }
            }
        }
    }

    // write conv output (coalesced per channel) + GN partials
#pragma unroll
    for (int i = 0; i < 32; i++) {
        float2 v = unpack2(acc[i]);
        g_conv_out[(size_t)(b*Cout + 2*i    )*Ss + rr] = v.x;
        g_conv_out[(size_t)(b*Cout + 2*i + 1)*Ss + rr] = v.y;
    }

    int lane = tid & 31, wid = tid >> 5;
#pragma unroll
    for (int g = 0; g < 16; g++) {
        float2 v0 = unpack2(acc[2*g]);
        float2 v1 = unpack2(acc[2*g + 1]);
        float s = v0.x + v0.y + v1.x + v1.y;
        float q = v0.x*v0.x + v0.y*v0.y + v1.x*v1.x + v1.y*v1.y;
        s += __shfl_down_sync(0xffffffffu, s, 16);
        q += __shfl_down_sync(0xffffffffu, q, 16);
        s += __shfl_down_sync(0xffffffffu, s, 8);
        q += __shfl_down_sync(0xffffffffu, q, 8);
        s += __shfl_down_sync(0xffffffffu, s, 4);
        q += __shfl_down_sync(0xffffffffu, q, 4);
        s += __shfl_down_sync(0xffffffffu, s, 2);
        q += __shfl_down_sync(0xffffffffu, q, 2);
        s += __shfl_down_sync(0xffffffffu, s, 1);
        q += __shfl_down_sync(0xffffffffu, q, 1);
        if (lane == 0) { s_warp[wid][g] = s; s_warp[wid][16 + g] = q; }
    }
    __syncthreads();
    if (tid < 32) {
        int blkb = blockIdx.x - b*BPB;
        g_gn_part[(size_t)(b*32 + tid)*BPB + blkb] =
            s_warp[0][tid] + s_warp[1][tid] + s_warp[2][tid] + s_warp[3][tid];
    }
}

// ---------------- kernel 5a: deterministic GN partial reduce ----------------
__global__ void k_gnred() {
    __shared__ float sh[256];
    int s = blockIdx.x;                   // 0..63 = b*32 + slot
    float a = 0.f;
    for (int i = threadIdx.x; i < BPB; i += 256)
        a += g_gn_part[(size_t)s*BPB + i];
    sh[threadIdx.x] = a;
    __syncthreads();
    for (int st = 128; st; st >>= 1) {
        if (threadIdx.x < st) sh[threadIdx.x] += sh[threadIdx.x + st];
        __syncthreads();
    }
    if (threadIdx.x == 0) g_gn_red[s] = sh[0];
}

// ---------------- kernel 5b: GN finalize (per (b,channel) affine) ----------------
__global__ void k_gnfin(const float* __restrict__ gng, const float* __restrict__ gnb) {
    int t = threadIdx.x;
    if (t < Bn*Cout) {
        int b = t >> 6, o = t & 63, g = o >> 2;
        float n    = 4.f * (float)Ss;
        float mean = g_gn_red[b*32 + g] / n;
        float var  = g_gn_red[b*32 + 16 + g] / n - mean*mean;
        float a    = gng[o] * rsqrtf(fmaxf(var, 0.f) + EPSf);
        g_gn_a[t] = a;
        g_gn_b[t] = gnb[o] - mean * a;
    }
}

// ---------------- kernel 6: GN apply + ReLU ----------------
__global__ void k_gnapply(float* __restrict__ out) {
    int i = blockIdx.x * 256 + threadIdx.x;
    if (i >= (Bn*Cout*Ss) / 4) return;
    int cidx = i / (Ss / 4);
    float a = g_gn_a[cidx], bsh = g_gn_b[cidx];
    float4 v = reinterpret_cast<const float4*>(g_conv_out)[i];
    float4 r;
    r.x = fmaxf(fmaf(v.x, a, bsh), 0.f);
    r.y = fmaxf(fmaf(v.y, a, bsh), 0.f);
    r.z = fmaxf(fmaf(v.z, a, bsh), 0.f);
    r.w = fmaxf(fmaf(v.w, a, bsh), 0.f);
    reinterpret_cast<float4*>(out)[i] = r;
}

// ---------------- launch ----------------
extern "C" void kernel_launch(void* const* d_in, const int* in_sizes, int n_in,
                              void* d_out, int out_size) {
    const float* x   = (const float*)d_in[0];
    const float* ow  = (const float*)d_in[1];
    const float* ob  = (const float*)d_in[2];
    const float* bng = (const float*)d_in[3];
    const float* bnb = (const float*)d_in[4];
    const float* cw  = (const float*)d_in[5];
    const float* cb  = (const float*)d_in[6];
    const float* gng = (const float*)d_in[7];
    const float* gnb = (const float*)d_in[8];

    k_transpose<<<Bn*Dd*Hh*2, dim3(32, 32)>>>(x);
    k_offconv<<<NBLK, 128>>>(ow, ob);
    k_bnred<<<12, 256>>>();
    k_bnfin<<<1, 32>>>(bng, bnb);
    k_sampconv<<<NBLK, 128>>>(cw, cb);
    k_gnred<<<64, 256>>>();
    k_gnfin<<<1, 128>>>(gng, gnb);
    k_gnapply<<<(Bn*Cout*Ss/4 + 255)/256, 256>>>((float*)d_out);
}

// round 12
// speedup vs baseline: 1.6860x; 1.6860x over previous
#include <cuda_runtime.h>
#include <math.h>

// ---------------- problem constants ----------------
#define Bn    2
#define Cin   32
#define Cout  64
#define Dd    48
#define Hh    48
#define Ww    48
#define HWc   (Hh*Ww)          // 2304
#define Ss    (Dd*Hh*Ww)       // 110592
#define NPTS  (Bn*Ss)          // 221184
#define NBLK  (NPTS/128)       // 1728 point-kernel blocks
#define BPB   (Ss/128)         // 864 blocks per batch
#define EPSf  1e-5f

// ---------------- scratch (no runtime allocation) ----------------
__device__ float g_off_raw[Bn*6*Ss];       // raw offset-conv, channels 3..8 ~5.3MB
__device__ float g_conv_out[Bn*Cout*Ss];   // pre-GN conv output ~56.6MB
__device__ float g_bn_part[12*NBLK];
__device__ float g_bn_red[12];
__device__ float g_bn_scale[6];
__device__ float g_bn_shift[6];
__device__ float g_gn_part[64*BPB];        // (b*32 + slot)*BPB + blk
__device__ float g_gn_red[64];
__device__ float g_gn_a[Bn*Cout];
__device__ float g_gn_b[Bn*Cout];

// ---------------- packed f32x2 helpers ----------------
__device__ __forceinline__ unsigned long long pack2(float x, float y) {
    unsigned long long r;
    asm("mov.b64 %0, {%1, %2};" : "=l"(r) : "f"(x), "f"(y));
    return r;
}
__device__ __forceinline__ float2 unpack2(unsigned long long v) {
    float2 r;
    asm("mov.b64 {%0, %1}, %2;" : "=f"(r.x), "=f"(r.y) : "l"(v));
    return r;
}
__device__ __forceinline__ void ffma2u(unsigned long long& d,
                                       unsigned long long a,
                                       unsigned long long b) {
    asm("fma.rn.f32x2 %0, %1, %2, %0;" : "+l"(d) : "l"(a), "l"(b));
}

// ---------------- kernel 1: offset conv (3x3x3, SAME), 6 live channels ----------------
// Channel-major x; lanes along w -> all LDG coalesced. f32x2 lanes = channel pairs.
__global__ void __launch_bounds__(128) k_offconv(const float* __restrict__ x,
                                                 const float* __restrict__ ow,
                                                 const float* __restrict__ ob) {
    __shared__ __align__(16) unsigned long long s_w[27*16*6];  // [(tap*16+c2)*6 + j]
    __shared__ float s_bias[6];
    __shared__ float s_warp[4][12];

    int tid = threadIdx.x;
    for (int idx = tid; idx < 27*16*6; idx += 128) {
        int j   = idx % 6;
        int c2  = (idx / 6) % 16;
        int tap = idx / 96;
        s_w[idx] = pack2(ow[(3+j)*(Cin*27) + (2*c2  )*27 + tap],
                         ow[(3+j)*(Cin*27) + (2*c2+1)*27 + tap]);
    }
    if (tid < 6) s_bias[tid] = ob[3+tid];
    __syncthreads();

    int p  = blockIdx.x * 128 + tid;
    int b  = p / Ss;
    int rr = p - b*Ss;
    int d  = rr / HWc;
    int hw = rr - d*HWc;
    int h  = hw / Ww;
    int w  = hw - h*Ww;

    unsigned long long acc[6] = {0ULL,0ULL,0ULL,0ULL,0ULL,0ULL};
    const float* xb = x + b*(Cin*Ss);

#pragma unroll 1
    for (int kd = 0; kd < 3; kd++) {
        int zz = d + kd - 1; if ((unsigned)zz >= Dd) continue;
#pragma unroll 1
        for (int kh = 0; kh < 3; kh++) {
            int yy = h + kh - 1; if ((unsigned)yy >= Hh) continue;
#pragma unroll 1
            for (int kw = 0; kw < 3; kw++) {
                int xx = w + kw - 1; if ((unsigned)xx >= Ww) continue;
                int tap = (kd*3 + kh)*3 + kw;
                const float* xp = xb + (zz*HWc + yy*Ww + xx);
                const ulonglong2* wq = (const ulonglong2*)&s_w[tap*96];
#pragma unroll
                for (int c2 = 0; c2 < 16; c2++) {
                    float v0 = xp[0];
                    float v1 = xp[Ss];
                    xp += 2*Ss;
                    unsigned long long sv = pack2(v0, v1);
                    ulonglong2 a0 = wq[0], a1 = wq[1], a2 = wq[2];
                    wq += 3;
                    ffma2u(acc[0], sv, a0.x); ffma2u(acc[1], sv, a0.y);
                    ffma2u(acc[2], sv, a1.x); ffma2u(acc[3], sv, a1.y);
                    ffma2u(acc[4], sv, a2.x); ffma2u(acc[5], sv, a2.y);
                }
            }
        }
    }

    float red[12];
#pragma unroll
    for (int j = 0; j < 6; j++) {
        float2 a = unpack2(acc[j]);
        float v = a.x + a.y + s_bias[j];   // even-channel + odd-channel partials
        g_off_raw[(b*6 + j)*Ss + rr] = v;
        red[j]     = v;
        red[6 + j] = v * v;
    }

    int lane = tid & 31, wid = tid >> 5;
#pragma unroll
    for (int r = 0; r < 12; r++) {
        float t = red[r];
        t += __shfl_down_sync(0xffffffffu, t, 16);
        t += __shfl_down_sync(0xffffffffu, t, 8);
        t += __shfl_down_sync(0xffffffffu, t, 4);
        t += __shfl_down_sync(0xffffffffu, t, 2);
        t += __shfl_down_sync(0xffffffffu, t, 1);
        if (lane == 0) s_warp[wid][r] = t;
    }
    __syncthreads();
    if (tid < 12)
        g_bn_part[tid*NBLK + blockIdx.x] =
            s_warp[0][tid] + s_warp[1][tid] + s_warp[2][tid] + s_warp[3][tid];
}

// ---------------- kernel 2a: deterministic BN partial reduce ----------------
__global__ void k_bnred() {
    __shared__ float sh[256];
    int s = blockIdx.x;                   // 0..11
    float a = 0.f;
    for (int i = threadIdx.x; i < NBLK; i += 256)
        a += g_bn_part[s*NBLK + i];
    sh[threadIdx.x] = a;
    __syncthreads();
    for (int st = 128; st; st >>= 1) {
        if (threadIdx.x < st) sh[threadIdx.x] += sh[threadIdx.x + st];
        __syncthreads();
    }
    if (threadIdx.x == 0) g_bn_red[s] = sh[0];
}

// ---------------- kernel 2b: BN finalize ----------------
__global__ void k_bnfin(const float* __restrict__ bng, const float* __restrict__ bnb) {
    int j = threadIdx.x;
    if (j < 6) {
        float n    = (float)NPTS;
        float mean = g_bn_red[j] / n;
        float var  = g_bn_red[6 + j] / n - mean*mean;
        float sc   = bng[3 + j] * rsqrtf(fmaxf(var, 0.f) + EPSf);
        g_bn_scale[j] = sc;
        g_bn_shift[j] = bnb[3 + j] - mean * sc;
    }
}

// ---------------- kernel 3: fused BN+tanh+offsets+bilinear sample+1x1xK conv ----------------
// Channel-major gathers (scalar, coalesced); f32x2 lanes = output pairs.
__global__ void __launch_bounds__(128) k_sampconv(const float* __restrict__ x,
                                                  const float* __restrict__ cw,
                                                  const float* __restrict__ cb) {
    __shared__ __align__(16) unsigned long long s_cw[3*32*32];  // [(k*32+c)*32 + j]
    __shared__ unsigned long long s_cb[32];
    __shared__ float s_warp[4][32];

    int tid = threadIdx.x;
    for (int idx = tid; idx < 3072; idx += 128) {
        int j = idx & 31;
        int c = (idx >> 5) & 31;
        int k = idx >> 10;
        s_cw[idx] = pack2(cw[(2*j  )*96 + c*3 + k],
                          cw[(2*j+1)*96 + c*3 + k]);
    }
    if (tid < 32) s_cb[tid] = pack2(cb[2*tid], cb[2*tid+1]);
    __syncthreads();

    int p  = blockIdx.x * 128 + tid;
    int b  = p / Ss;
    int rr = p - b*Ss;
    int d  = rr / HWc;
    int hw = rr - d*HWc;
    int h  = hw / Ww;
    int w  = hw - h*Ww;

    // BN + tanh on the 6 live offset channels
    float off[6];
#pragma unroll
    for (int j = 0; j < 6; j++) {
        float raw = g_off_raw[(b*6 + j)*Ss + rr];
        off[j] = tanhf(fmaf(raw, g_bn_scale[j], g_bn_shift[j]));
    }
    // K=3 cumulative offsets: center k=1 is zero, edges are single taps
    float cy[3] = { off[0], 0.f, off[2] };
    float cx[3] = { off[3], 0.f, off[5] };

    unsigned long long acc[32];
#pragma unroll
    for (int j = 0; j < 32; j++) acc[j] = s_cb[j];

    const float* xb = x + b*(Cin*Ss);

#pragma unroll 1
    for (int k = 0; k < 3; k++) {
        int z = d + k - 1;
        z = max(0, min(z, Dd - 1));                         // integer z -> bilinear
        float yf = fminf(fmaxf((float)h + cy[k], 0.f), (float)(Hh - 1));
        float xf = fminf(fmaxf((float)w + cx[k], 0.f), (float)(Ww - 1));
        float y0f = floorf(yf), x0f = floorf(xf);
        float wy = yf - y0f, wx = xf - x0f;
        int y0 = (int)y0f, x0 = (int)x0f;
        int y1 = min(y0 + 1, Hh - 1), x1 = min(x0 + 1, Ww - 1);
        float w00 = (1.f - wy) * (1.f - wx);
        float w01 = (1.f - wy) * wx;
        float w10 = wy * (1.f - wx);
        float w11 = wy * wx;

        const float* q00 = xb + (z*HWc + y0*Ww + x0);
        const float* q01 = xb + (z*HWc + y0*Ww + x1);
        const float* q10 = xb + (z*HWc + y1*Ww + x0);
        const float* q11 = xb + (z*HWc + y1*Ww + x1);
        const ulonglong2* wk = (const ulonglong2*)&s_cw[k*1024];

#pragma unroll 4
        for (int c = 0; c < 32; c++) {
            float a0 = q00[0], a1 = q01[0], a2 = q10[0], a3 = q11[0];
            q00 += Ss; q01 += Ss; q10 += Ss; q11 += Ss;
            float s = fmaf(w00, a0, fmaf(w01, a1, fmaf(w10, a2, w11 * a3)));
            unsigned long long sv = pack2(s, s);
#pragma unroll
            for (int i = 0; i < 16; i++) {
                ulonglong2 ww = wk[i];
                ffma2u(acc[2*i  ], sv, ww.x);
                ffma2u(acc[2*i+1], sv, ww.y);
            }
            wk += 16;
        }
    }

    // write conv output (coalesced per channel) + GN partials
#pragma unroll
    for (int j = 0; j < 32; j++) {
        float2 v = unpack2(acc[j]);
        g_conv_out[(b*Cout + 2*j    )*Ss + rr] = v.x;
        g_conv_out[(b*Cout + 2*j + 1)*Ss + rr] = v.y;
    }

    int lane = tid & 31, wid = tid >> 5;
#pragma unroll
    for (int g = 0; g < 16; g++) {
        float2 v0 = unpack2(acc[2*g]);
        float2 v1 = unpack2(acc[2*g + 1]);
        float s = v0.x + v0.y + v1.x + v1.y;
        float q = v0.x*v0.x + v0.y*v0.y + v1.x*v1.x + v1.y*v1.y;
        s += __shfl_down_sync(0xffffffffu, s, 16);
        q += __shfl_down_sync(0xffffffffu, q, 16);
        s += __shfl_down_sync(0xffffffffu, s, 8);
        q += __shfl_down_sync(0xffffffffu, q, 8);
        s += __shfl_down_sync(0xffffffffu, s, 4);
        q += __shfl_down_sync(0xffffffffu, q, 4);
        s += __shfl_down_sync(0xffffffffu, s, 2);
        q += __shfl_down_sync(0xffffffffu, q, 2);
        s += __shfl_down_sync(0xffffffffu, s, 1);
        q += __shfl_down_sync(0xffffffffu, q, 1);
        if (lane == 0) { s_warp[wid][g] = s; s_warp[wid][16 + g] = q; }
    }
    __syncthreads();
    if (tid < 32) {
        int blkb = blockIdx.x - b*BPB;
        g_gn_part[(b*32 + tid)*BPB + blkb] =
            s_warp[0][tid] + s_warp[1][tid] + s_warp[2][tid] + s_warp[3][tid];
    }
}

// ---------------- kernel 4a: deterministic GN partial reduce ----------------
__global__ void k_gnred() {
    __shared__ float sh[256];
    int s = blockIdx.x;                   // 0..63 = b*32 + slot
    float a = 0.f;
    for (int i = threadIdx.x; i < BPB; i += 256)
        a += g_gn_part[s*BPB + i];
    sh[threadIdx.x] = a;
    __syncthreads();
    for (int st = 128; st; st >>= 1) {
        if (threadIdx.x < st) sh[threadIdx.x] += sh[threadIdx.x + st];
        __syncthreads();
    }
    if (threadIdx.x == 0) g_gn_red[s] = sh[0];
}

// ---------------- kernel 4b: GN finalize (per (b,channel) affine) ----------------
__global__ void k_gnfin(const float* __restrict__ gng, const float* __restrict__ gnb) {
    int t = threadIdx.x;
    if (t < Bn*Cout) {
        int b = t >> 6, o = t & 63, g = o >> 2;
        float n    = 4.f * (float)Ss;
        float mean = g_gn_red[b*32 + g] / n;
        float var  = g_gn_red[b*32 + 16 + g] / n - mean*mean;
        float a    = gng[o] * rsqrtf(fmaxf(var, 0.f) + EPSf);
        g_gn_a[t] = a;
        g_gn_b[t] = gnb[o] - mean * a;
    }
}

// ---------------- kernel 5: GN apply + ReLU ----------------
__global__ void k_gnapply(float* __restrict__ out) {
    int i = blockIdx.x * 256 + threadIdx.x;
    if (i >= (Bn*Cout*Ss) / 4) return;
    int cidx = i / (Ss / 4);
    float a = g_gn_a[cidx], bsh = g_gn_b[cidx];
    float4 v = reinterpret_cast<const float4*>(g_conv_out)[i];
    float4 r;
    r.x = fmaxf(fmaf(v.x, a, bsh), 0.f);
    r.y = fmaxf(fmaf(v.y, a, bsh), 0.f);
    r.z = fmaxf(fmaf(v.z, a, bsh), 0.f);
    r.w = fmaxf(fmaf(v.w, a, bsh), 0.f);
    reinterpret_cast<float4*>(out)[i] = r;
}

// ---------------- launch ----------------
extern "C" void kernel_launch(void* const* d_in, const int* in_sizes, int n_in,
                              void* d_out, int out_size) {
    const float* x   = (const float*)d_in[0];
    const float* ow  = (const float*)d_in[1];
    const float* ob  = (const float*)d_in[2];
    const float* bng = (const float*)d_in[3];
    const float* bnb = (const float*)d_in[4];
    const float* cw  = (const float*)d_in[5];
    const float* cb  = (const float*)d_in[6];
    const float* gng = (const float*)d_in[7];
    const float* gnb = (const float*)d_in[8];

    k_offconv<<<NBLK, 128>>>(x, ow, ob);
    k_bnred<<<12, 256>>>();
    k_bnfin<<<1, 32>>>(bng, bnb);
    k_sampconv<<<NBLK, 128>>>(x, cw, cb);
    k_gnred<<<64, 256>>>();
    k_gnfin<<<1, 128>>>(gng, gnb);
    k_gnapply<<<(Bn*Cout*Ss/4 + 255)/256, 256>>>((float*)d_out);
}